// round 15
// baseline (speedup 1.0000x reference)
#include <cuda_runtime.h>
#include <math.h>

#define H 1024
#define E 512
#define A 512
#define L 512
#define V 50257
#define NPART 32

// K1': scores[0,32) + apply[32,64) + ghh[64,320) + combp[320,384)
#define S_BLKS  32
#define AP_BLKS 32
#define GH_BLKS 256
#define CP_BLKS 64
#define K1_BLKS (S_BLKS + AP_BLKS + GH_BLKS + CP_BLKS)
// K34': comb[0,64) + gates[64,320)
#define CB_BLKS 64
#define GT_BLKS 256
#define K34_BLKS (CB_BLKS + GT_BLKS)
// K5: single-wave grid-stride, 4 rows/warp per iteration
#define K5_BLKS 592
#define K5_SWEEP (K5_BLKS * 8 * 4)     // 18944 rows per sweep

// tail prefetch: all 592 k5 blocks x 64KB = last 37MB of out_W
#define TPF_CHUNK  65536
#define OUTW_BYTES ((size_t)V * H * 4)
#define TPF_START  (OUTW_BYTES - (size_t)K5_BLKS * TPF_CHUNK)

// ---------------- scratch (device globals) ----------------------------------
__device__ __align__(16) float g_scores[L];
__device__ __align__(16) float g_part[NPART * H];
__device__ __align__(16) float g_ghh[4 * H];
__device__ __align__(16) float g_xpart[H];
__device__ __align__(16) float g_x[H];
__device__ __align__(16) float g_gates[4 * H];
__device__ __align__(16) float g_h[H];
__device__ unsigned g_sem_scores;
__device__ unsigned g_sem_x;
__device__ unsigned g_sem_lstm;

__device__ __forceinline__ float warp_sum(float v) {
#pragma unroll
    for (int o = 16; o > 0; o >>= 1) v += __shfl_down_sync(0xffffffffu, v, o);
    return v;
}
__device__ __forceinline__ void fma4(float& s, float4 a, float4 c) {
    s += a.x * c.x + a.y * c.y + a.z * c.z + a.w * c.w;
}
__device__ __forceinline__ void pdl_trigger() {
    asm volatile("griddepcontrol.launch_dependents;" ::: "memory");
}
__device__ __forceinline__ void pdl_wait() {
    asm volatile("griddepcontrol.wait;" ::: "memory");
}
__device__ __forceinline__ void pf_last(const void* p) {
    asm volatile("prefetch.global.L2::evict_last [%0];" :: "l"(p));
}
__device__ __forceinline__ void sem_spin(unsigned* sem, unsigned target) {
    if (threadIdx.x == 0) {
        while (atomicAdd(sem, 0u) < target) __nanosleep(64);
        __threadfence();
    }
    __syncthreads();
}

// ============ K1': scores + apply (fused via semaphore) + ghh + combp =======
__global__ __launch_bounds__(256) void k1_pre(
        const int* __restrict__ word, const float* __restrict__ emb,
        const float* __restrict__ h0, const float* __restrict__ av,
        const float* __restrict__ attn_W, const float* __restrict__ attn_b,
        const float* __restrict__ W_hh, const float* __restrict__ comb_W,
        const float* __restrict__ enc, float* __restrict__ d_attn_out) {
    pdl_trigger();
    __shared__ float sc[E + H];
    __shared__ float sred[8];
    __shared__ float sbc;
    int t = threadIdx.x, lane = t & 31, w = t >> 5, b = blockIdx.x;

    if (b < S_BLKS) {
        long wrow = (long)word[0] * E;
        for (int i = t; i < E + H; i += 256)
            sc[i] = (i < E) ? emb[wrow + i] : h0[i - E];
        __syncthreads();
        int u = b * 8 + w;                       // [0,256)
        int r0 = u, r1 = u + 256;
        const float4* w0 = reinterpret_cast<const float4*>(attn_W) + (size_t)r0 * 384;
        const float4* w1 = reinterpret_cast<const float4*>(attn_W) + (size_t)r1 * 384;
        const float4* vv = reinterpret_cast<const float4*>(sc);
        float s0 = 0.f, s1 = 0.f;
#pragma unroll
        for (int i = 0; i < 12; i++) {
            float4 a = __ldcs(&w0[lane + 32 * i]);
            float4 a2 = __ldcs(&w1[lane + 32 * i]);
            float4 c = vv[lane + 32 * i];
            fma4(s0, a, c); fma4(s1, a2, c);
        }
        s0 = warp_sum(s0); s1 = warp_sum(s1);
        if (lane == 0) {
            g_scores[r0] = s0 + attn_b[r0];
            g_scores[r1] = s1 + attn_b[r1];
        }
        __syncthreads();
        if (t == 0) {
            __threadfence();
            atomicAdd(&g_sem_scores, 1u);
        }
    } else if (b < S_BLKS + AP_BLKS) {
        int ab = b - S_BLKS;                     // [0,32)
        int l0 = ab * 16;
        float4 ereg[16];
        const float4* e4 = reinterpret_cast<const float4*>(enc);
#pragma unroll
        for (int l = 0; l < 16; l++)
            ereg[l] = __ldcs(&e4[(size_t)(l0 + l) * 256 + t]);

        sem_spin(&g_sem_scores, S_BLKS);

        float v0 = g_scores[t], v1 = g_scores[t + 256];
        float m = fmaxf(v0, v1);
#pragma unroll
        for (int o = 16; o > 0; o >>= 1) m = fmaxf(m, __shfl_xor_sync(0xffffffffu, m, o));
        if (lane == 0) sred[w] = m;
        __syncthreads();
        if (t == 0) {
            float mm = sred[0];
#pragma unroll
            for (int i = 1; i < 8; i++) mm = fmaxf(mm, sred[i]);
            sbc = mm;
        }
        __syncthreads();
        float bmax = sbc;
        float e0 = expf(v0 - bmax), e1 = expf(v1 - bmax);
        float su = e0 + e1;
#pragma unroll
        for (int o = 16; o > 0; o >>= 1) su += __shfl_xor_sync(0xffffffffu, su, o);
        __syncthreads();
        if (lane == 0) sred[w] = su;
        __syncthreads();
        if (t == 0) {
            float ss = 0.f;
#pragma unroll
            for (int i = 0; i < 8; i++) ss += sred[i];
            sbc = ss;
        }
        __syncthreads();
        float inv = 1.0f / sbc;
        float w0 = e0 * inv, w1 = e1 * inv;
        sc[t] = w0; sc[t + 256] = w1;
        if (ab == 0) { d_attn_out[t] = w0; d_attn_out[t + 256] = w1; }
        __syncthreads();

        float4 acc = make_float4(0.f, 0.f, 0.f, 0.f);
#pragma unroll
        for (int l = 0; l < 16; l++) {
            float wk = sc[l0 + l];
            acc.x += wk * ereg[l].x; acc.y += wk * ereg[l].y;
            acc.z += wk * ereg[l].z; acc.w += wk * ereg[l].w;
        }
        reinterpret_cast<float4*>(g_part)[ab * 256 + t] = acc;
    } else if (b < S_BLKS + AP_BLKS + GH_BLKS) {
        for (int i = t; i < H; i += 256) sc[i] = h0[i];
        __syncthreads();
        int u = (b - S_BLKS - AP_BLKS) * 8 + w;  // [0,2048)
        int r0 = u, r1 = u + 2048;
        const float4* w0 = reinterpret_cast<const float4*>(W_hh) + (size_t)r0 * 256;
        const float4* w1 = reinterpret_cast<const float4*>(W_hh) + (size_t)r1 * 256;
        const float4* vv = reinterpret_cast<const float4*>(sc);
        float s0 = 0.f, s1 = 0.f;
#pragma unroll
        for (int i = 0; i < 8; i++) {
            float4 a = __ldcs(&w0[lane + 32 * i]);
            float4 a2 = __ldcs(&w1[lane + 32 * i]);
            float4 c = vv[lane + 32 * i];
            fma4(s0, a, c); fma4(s1, a2, c);
        }
        s0 = warp_sum(s0); s1 = warp_sum(s1);
        if (lane == 0) { g_ghh[r0] = s0; g_ghh[r1] = s1; }
    } else {
        long wrow = (long)word[0] * E;
        for (int i = t; i < E; i += 256) { sc[i] = emb[wrow + i]; sc[E + i] = av[i]; }
        __syncthreads();
        int u = (b - S_BLKS - AP_BLKS - GH_BLKS) * 8 + w;   // [0,512)
        int r0 = u, r1 = u + 512;
        const float4* w0 = reinterpret_cast<const float4*>(comb_W) + (size_t)r0 * 512;
        const float4* w1 = reinterpret_cast<const float4*>(comb_W) + (size_t)r1 * 512;
        const float4* vv = reinterpret_cast<const float4*>(sc);
        float s0 = 0.f, s1 = 0.f;
#pragma unroll
        for (int i = 0; i < 4; i++) {
            float4 c = vv[lane + 32 * i];
            float4 c2 = vv[128 + lane + 32 * i];
            float4 a = __ldcs(&w0[lane + 32 * i]);
            float4 a2 = __ldcs(&w1[lane + 32 * i]);
            float4 d = __ldcs(&w0[384 + lane + 32 * i]);
            float4 d2 = __ldcs(&w1[384 + lane + 32 * i]);
            fma4(s0, a, c);  fma4(s1, a2, c);
            fma4(s0, d, c2); fma4(s1, d2, c2);
        }
        s0 = warp_sum(s0); s1 = warp_sum(s1);
        if (lane == 0) { g_xpart[r0] = s0; g_xpart[r1] = s1; }
    }
}

// ============ K34': comb + gates (fused via semaphore) + LSTM ================
__global__ __launch_bounds__(256) void k34_mid(
        const float* __restrict__ comb_W, const float* __restrict__ comb_b,
        const float* __restrict__ W_ih, const float* __restrict__ b_ih,
        const float* __restrict__ b_hh, const float* __restrict__ c0,
        float* __restrict__ d_h, float* __restrict__ d_c) {
    pdl_trigger();
    int t = threadIdx.x, lane = t & 31, w = t >> 5, b = blockIdx.x;

    if (b < CB_BLKS) {
        int u = b * 8 + w;                       // [0,512)
        int r0 = u, r1 = u + 512;
        const float4* w0 = reinterpret_cast<const float4*>(comb_W) + (size_t)r0 * 512 + 128;
        const float4* w1 = reinterpret_cast<const float4*>(comb_W) + (size_t)r1 * 512 + 128;
        float4 wreg0[8], wreg1[8];
#pragma unroll
        for (int i = 0; i < 8; i++) {
            wreg0[i] = __ldcs(&w0[lane + 32 * i]);
            wreg1[i] = __ldcs(&w1[lane + 32 * i]);
        }
        pdl_wait();

        __shared__ float4 sat[256];
        if (t < 256) {
            float4 acc = make_float4(0.f, 0.f, 0.f, 0.f);
            const float4* p4 = reinterpret_cast<const float4*>(g_part);
#pragma unroll
            for (int p = 0; p < NPART; p++) {
                float4 x = p4[p * 256 + t];
                acc.x += x.x; acc.y += x.y; acc.z += x.z; acc.w += x.w;
            }
            sat[t] = acc;
        }
        __syncthreads();
        float s0 = 0.f, s1 = 0.f;
#pragma unroll
        for (int i = 0; i < 8; i++) {
            float4 c = sat[lane + 32 * i];
            fma4(s0, wreg0[i], c);
            fma4(s1, wreg1[i], c);
        }
        s0 = warp_sum(s0); s1 = warp_sum(s1);
        if (lane == 0) {
            g_x[r0] = fmaxf(s0 + g_xpart[r0] + comb_b[r0], 0.f);
            g_x[r1] = fmaxf(s1 + g_xpart[r1] + comb_b[r1], 0.f);
        }
        __syncthreads();
        if (t == 0) {
            __threadfence();
            atomicAdd(&g_sem_x, 1u);
        }
    } else {
        int u = (b - CB_BLKS) * 8 + w;           // [0,2048)
        int r0 = u, r1 = u + 2048;
        const float4* w0 = reinterpret_cast<const float4*>(W_ih) + (size_t)r0 * 256;
        const float4* w1 = reinterpret_cast<const float4*>(W_ih) + (size_t)r1 * 256;
        float4 wreg0[8], wreg1[8];
#pragma unroll
        for (int i = 0; i < 8; i++) {
            wreg0[i] = __ldcs(&w0[lane + 32 * i]);
            wreg1[i] = __ldcs(&w1[lane + 32 * i]);
        }
        pdl_wait();
        sem_spin(&g_sem_x, CB_BLKS);

        __shared__ float4 sx[256];
        __shared__ bool s_last;
        if (t < 256) sx[t] = reinterpret_cast<const float4*>(g_x)[t];
        __syncthreads();
        float s0 = 0.f, s1 = 0.f;
#pragma unroll
        for (int i = 0; i < 8; i++) {
            float4 c = sx[lane + 32 * i];
            fma4(s0, wreg0[i], c);
            fma4(s1, wreg1[i], c);
        }
        s0 = warp_sum(s0); s1 = warp_sum(s1);
        if (lane == 0) {
            g_gates[r0] = s0 + g_ghh[r0] + b_ih[r0] + b_hh[r0];
            g_gates[r1] = s1 + g_ghh[r1] + b_ih[r1] + b_hh[r1];
        }
        __syncthreads();

        if (t == 0) {
            __threadfence();
            unsigned old = atomicAdd(&g_sem_lstm, 1u);
            s_last = (old == GT_BLKS - 1);
            if (s_last) {
                g_sem_lstm = 0;
                g_sem_x = 0;
                g_sem_scores = 0;
            }
        }
        __syncthreads();
        if (s_last) {
            __threadfence();
#pragma unroll
            for (int r = 0; r < 4; r++) {
                int k = t + 256 * r;
                float gi = g_gates[k];
                float gf = g_gates[H + k];
                float gg = g_gates[2 * H + k];
                float go = g_gates[3 * H + k];
                float si = 1.f / (1.f + expf(-gi));
                float sf = 1.f / (1.f + expf(-gf));
                float so = 1.f / (1.f + expf(-go));
                float cn = sf * c0[k] + si * tanhf(gg);
                float hn = so * tanhf(cn);
                g_h[k] = hn;
                d_h[k] = hn;
                d_c[k] = cn;
            }
        }
    }
}

// ============ K5: logits — single-wave grid-stride, 4 rows/warp/iter ========
__global__ __launch_bounds__(256) void k5_logits(
        const float* __restrict__ out_W, const float* __restrict__ out_b,
        float* __restrict__ logits) {
    int t = threadIdx.x, lane = t & 31, w = t >> 5;

    // prologue: every block prefetches 64KB of the tail 37MB of out_W into
    // L2 (evict_last) during the pre-logits window; those rows are read in
    // the final sweep iteration, when DRAM is saturated.
    {
        const char* p = (const char*)out_W + TPF_START
                        + (size_t)blockIdx.x * TPF_CHUNK + (size_t)t * 256;
        pf_last(p);
        pf_last(p + 128);
    }
    pdl_wait();

    __shared__ float4 sh[H / 4];
    sh[t] = reinterpret_cast<const float4*>(g_h)[t];
    __syncthreads();

    for (int base = (blockIdx.x * 8 + w) * 4; base < V; base += K5_SWEEP) {
        int r0 = base, r1 = base + 1, r2 = base + 2, r3 = base + 3;
        int c0 = r0 < V ? r0 : V - 1;
        int c1 = r1 < V ? r1 : V - 1;
        int c2 = r2 < V ? r2 : V - 1;
        int c3 = r3 < V ? r3 : V - 1;
        const float4* w0 = reinterpret_cast<const float4*>(out_W) + (size_t)c0 * 256;
        const float4* w1 = reinterpret_cast<const float4*>(out_W) + (size_t)c1 * 256;
        const float4* w2 = reinterpret_cast<const float4*>(out_W) + (size_t)c2 * 256;
        const float4* w3 = reinterpret_cast<const float4*>(out_W) + (size_t)c3 * 256;
        float s0 = 0.f, s1 = 0.f, s2 = 0.f, s3 = 0.f;
#pragma unroll
        for (int i = 0; i < 8; i++) {
            float4 a0 = __ldcs(&w0[lane + 32 * i]);
            float4 a1 = __ldcs(&w1[lane + 32 * i]);
            float4 a2 = __ldcs(&w2[lane + 32 * i]);
            float4 a3 = __ldcs(&w3[lane + 32 * i]);
            float4 h = sh[lane + 32 * i];
            fma4(s0, a0, h); fma4(s1, a1, h);
            fma4(s2, a2, h); fma4(s3, a3, h);
        }
        s0 = warp_sum(s0); s1 = warp_sum(s1);
        s2 = warp_sum(s2); s3 = warp_sum(s3);
        if (lane == 0) {
            if (r0 < V) logits[r0] = s0 + out_b[r0];
            if (r1 < V) logits[r1] = s1 + out_b[r1];
            if (r2 < V) logits[r2] = s2 + out_b[r2];
            if (r3 < V) logits[r3] = s3 + out_b[r3];
        }
    }
}

// ---------------- launch: 3-kernel PDL chain ---------------------------------
extern "C" void kernel_launch(void* const* d_in, const int* in_sizes, int n_in,
                              void* d_out, int out_size) {
    (void)out_size;
    const int* word = (const int*)d_in[0];
    int k = (n_in >= 2 && in_sizes[1] == 1) ? 2 : 1;
    const float* av_emb  = (const float*)d_in[k + 0];
    const float* h0      = (const float*)d_in[k + 1];
    const float* c0      = (const float*)d_in[k + 2];
    const float* enc_out = (const float*)d_in[k + 3];
    const float* emb     = (const float*)d_in[k + 4];
    const float* attn_W  = (const float*)d_in[k + 5];
    const float* attn_b  = (const float*)d_in[k + 6];
    const float* comb_W  = (const float*)d_in[k + 7];
    const float* comb_b  = (const float*)d_in[k + 8];
    const float* W_ih    = (const float*)d_in[k + 9];
    const float* W_hh    = (const float*)d_in[k + 10];
    const float* b_ih    = (const float*)d_in[k + 11];
    const float* b_hh    = (const float*)d_in[k + 12];
    const float* out_W   = (const float*)d_in[k + 13];
    const float* out_b   = (const float*)d_in[k + 14];

    float* out = (float*)d_out;
    float* o_logits = out;              // [V]
    float* o_h      = out + V;          // [H]
    float* o_c      = out + V + H;      // [H]
    float* o_attn   = out + V + 2 * H;  // [L]

    cudaLaunchAttribute attr[1];
    attr[0].id = cudaLaunchAttributeProgrammaticStreamSerialization;
    attr[0].val.programmaticStreamSerializationAllowed = 1;

    cudaLaunchConfig_t cfg = {};
    cfg.blockDim = {256, 1, 1};
    cfg.dynamicSmemBytes = 0;
    cfg.stream = 0;
    cfg.attrs = attr;
    cfg.numAttrs = 1;

    k1_pre<<<K1_BLKS, 256>>>(word, emb, h0, av_emb, attn_W, attn_b, W_hh,
                             comb_W, enc_out, o_attn);

    cfg.gridDim = {K34_BLKS, 1, 1};
    cudaLaunchKernelEx(&cfg, k34_mid, comb_W, comb_b, W_ih, b_ih, b_hh, c0,
                       o_h, o_c);

    cfg.gridDim = {K5_BLKS, 1, 1};
    cudaLaunchKernelEx(&cfg, k5_logits, out_W, out_b, o_logits);
}

// round 16
// speedup vs baseline: 1.0696x; 1.0696x over previous
#include <cuda_runtime.h>
#include <math.h>

#define H 1024
#define E 512
#define A 512
#define L 512
#define V 50257
#define NPART 32

// K1': scores[0,32) + apply[32,64) + ghh[64,320) + combp[320,384)
#define S_BLKS  32
#define AP_BLKS 32
#define GH_BLKS 256
#define CP_BLKS 64
#define K1_BLKS (S_BLKS + AP_BLKS + GH_BLKS + CP_BLKS)
// K34': comb[0,64) + gates[64,320)
#define CB_BLKS 64
#define GT_BLKS 256
#define K34_BLKS (CB_BLKS + GT_BLKS)
// K5: 4 consecutive rows/warp, oversubscribed grid (R12/R14 form)
#define LOGIT_BLKS 1571

// tail prefetch: 640 early k5 blocks x 64KB = last 40MB of out_W
#define TPF_BLKS   640
#define TPF_CHUNK  65536
#define OUTW_BYTES ((size_t)V * H * 4)
#define TPF_START  (OUTW_BYTES - (size_t)TPF_BLKS * TPF_CHUNK)

// ---------------- scratch (device globals) ----------------------------------
__device__ __align__(16) float g_scores[L];
__device__ __align__(16) float g_part[NPART * H];
__device__ __align__(16) float g_ghh[4 * H];
__device__ __align__(16) float g_xpart[H];
__device__ __align__(16) float g_x[H];
__device__ __align__(16) float g_gates[4 * H];
__device__ __align__(16) float g_h[H];
__device__ unsigned g_sem_scores;
__device__ unsigned g_sem_x;
__device__ unsigned g_sem_lstm;

__device__ __forceinline__ float warp_sum(float v) {
#pragma unroll
    for (int o = 16; o > 0; o >>= 1) v += __shfl_down_sync(0xffffffffu, v, o);
    return v;
}
__device__ __forceinline__ void fma4(float& s, float4 a, float4 c) {
    s += a.x * c.x + a.y * c.y + a.z * c.z + a.w * c.w;
}
__device__ __forceinline__ void pdl_trigger() {
    asm volatile("griddepcontrol.launch_dependents;" ::: "memory");
}
__device__ __forceinline__ void pdl_wait() {
    asm volatile("griddepcontrol.wait;" ::: "memory");
}
__device__ __forceinline__ void pf_last(const void* p) {
    asm volatile("prefetch.global.L2::evict_last [%0];" :: "l"(p));
}
__device__ __forceinline__ void sem_spin(unsigned* sem, unsigned target) {
    if (threadIdx.x == 0) {
        while (atomicAdd(sem, 0u) < target) __nanosleep(64);
        __threadfence();
    }
    __syncthreads();
}

// ============ K1': scores + apply (fused via semaphore) + ghh + combp =======
__global__ __launch_bounds__(256) void k1_pre(
        const int* __restrict__ word, const float* __restrict__ emb,
        const float* __restrict__ h0, const float* __restrict__ av,
        const float* __restrict__ attn_W, const float* __restrict__ attn_b,
        const float* __restrict__ W_hh, const float* __restrict__ comb_W,
        const float* __restrict__ enc, float* __restrict__ d_attn_out) {
    pdl_trigger();
    __shared__ float sc[E + H];
    __shared__ float sred[8];
    __shared__ float sbc;
    int t = threadIdx.x, lane = t & 31, w = t >> 5, b = blockIdx.x;

    if (b < S_BLKS) {
        long wrow = (long)word[0] * E;
        for (int i = t; i < E + H; i += 256)
            sc[i] = (i < E) ? emb[wrow + i] : h0[i - E];
        __syncthreads();
        int u = b * 8 + w;                       // [0,256)
        int r0 = u, r1 = u + 256;
        const float4* w0 = reinterpret_cast<const float4*>(attn_W) + (size_t)r0 * 384;
        const float4* w1 = reinterpret_cast<const float4*>(attn_W) + (size_t)r1 * 384;
        const float4* vv = reinterpret_cast<const float4*>(sc);
        float s0 = 0.f, s1 = 0.f;
#pragma unroll
        for (int i = 0; i < 12; i++) {
            float4 a = __ldcs(&w0[lane + 32 * i]);
            float4 a2 = __ldcs(&w1[lane + 32 * i]);
            float4 c = vv[lane + 32 * i];
            fma4(s0, a, c); fma4(s1, a2, c);
        }
        s0 = warp_sum(s0); s1 = warp_sum(s1);
        if (lane == 0) {
            g_scores[r0] = s0 + attn_b[r0];
            g_scores[r1] = s1 + attn_b[r1];
        }
        __syncthreads();
        if (t == 0) {
            __threadfence();
            atomicAdd(&g_sem_scores, 1u);
        }
    } else if (b < S_BLKS + AP_BLKS) {
        int ab = b - S_BLKS;                     // [0,32)
        int l0 = ab * 16;
        float4 ereg[16];
        const float4* e4 = reinterpret_cast<const float4*>(enc);
#pragma unroll
        for (int l = 0; l < 16; l++)
            ereg[l] = __ldcs(&e4[(size_t)(l0 + l) * 256 + t]);

        sem_spin(&g_sem_scores, S_BLKS);

        float v0 = g_scores[t], v1 = g_scores[t + 256];
        float m = fmaxf(v0, v1);
#pragma unroll
        for (int o = 16; o > 0; o >>= 1) m = fmaxf(m, __shfl_xor_sync(0xffffffffu, m, o));
        if (lane == 0) sred[w] = m;
        __syncthreads();
        if (t == 0) {
            float mm = sred[0];
#pragma unroll
            for (int i = 1; i < 8; i++) mm = fmaxf(mm, sred[i]);
            sbc = mm;
        }
        __syncthreads();
        float bmax = sbc;
        float e0 = expf(v0 - bmax), e1 = expf(v1 - bmax);
        float su = e0 + e1;
#pragma unroll
        for (int o = 16; o > 0; o >>= 1) su += __shfl_xor_sync(0xffffffffu, su, o);
        __syncthreads();
        if (lane == 0) sred[w] = su;
        __syncthreads();
        if (t == 0) {
            float ss = 0.f;
#pragma unroll
            for (int i = 0; i < 8; i++) ss += sred[i];
            sbc = ss;
        }
        __syncthreads();
        float inv = 1.0f / sbc;
        float w0 = e0 * inv, w1 = e1 * inv;
        sc[t] = w0; sc[t + 256] = w1;
        if (ab == 0) { d_attn_out[t] = w0; d_attn_out[t + 256] = w1; }
        __syncthreads();

        float4 acc = make_float4(0.f, 0.f, 0.f, 0.f);
#pragma unroll
        for (int l = 0; l < 16; l++) {
            float wk = sc[l0 + l];
            acc.x += wk * ereg[l].x; acc.y += wk * ereg[l].y;
            acc.z += wk * ereg[l].z; acc.w += wk * ereg[l].w;
        }
        reinterpret_cast<float4*>(g_part)[ab * 256 + t] = acc;
    } else if (b < S_BLKS + AP_BLKS + GH_BLKS) {
        for (int i = t; i < H; i += 256) sc[i] = h0[i];
        __syncthreads();
        int u = (b - S_BLKS - AP_BLKS) * 8 + w;  // [0,2048)
        int r0 = u, r1 = u + 2048;
        const float4* w0 = reinterpret_cast<const float4*>(W_hh) + (size_t)r0 * 256;
        const float4* w1 = reinterpret_cast<const float4*>(W_hh) + (size_t)r1 * 256;
        const float4* vv = reinterpret_cast<const float4*>(sc);
        float s0 = 0.f, s1 = 0.f;
#pragma unroll
        for (int i = 0; i < 8; i++) {
            float4 a = __ldcs(&w0[lane + 32 * i]);
            float4 a2 = __ldcs(&w1[lane + 32 * i]);
            float4 c = vv[lane + 32 * i];
            fma4(s0, a, c); fma4(s1, a2, c);
        }
        s0 = warp_sum(s0); s1 = warp_sum(s1);
        if (lane == 0) { g_ghh[r0] = s0; g_ghh[r1] = s1; }
    } else {
        long wrow = (long)word[0] * E;
        for (int i = t; i < E; i += 256) { sc[i] = emb[wrow + i]; sc[E + i] = av[i]; }
        __syncthreads();
        int u = (b - S_BLKS - AP_BLKS - GH_BLKS) * 8 + w;   // [0,512)
        int r0 = u, r1 = u + 512;
        const float4* w0 = reinterpret_cast<const float4*>(comb_W) + (size_t)r0 * 512;
        const float4* w1 = reinterpret_cast<const float4*>(comb_W) + (size_t)r1 * 512;
        const float4* vv = reinterpret_cast<const float4*>(sc);
        float s0 = 0.f, s1 = 0.f;
#pragma unroll
        for (int i = 0; i < 4; i++) {
            float4 c = vv[lane + 32 * i];
            float4 c2 = vv[128 + lane + 32 * i];
            float4 a = __ldcs(&w0[lane + 32 * i]);
            float4 a2 = __ldcs(&w1[lane + 32 * i]);
            float4 d = __ldcs(&w0[384 + lane + 32 * i]);
            float4 d2 = __ldcs(&w1[384 + lane + 32 * i]);
            fma4(s0, a, c);  fma4(s1, a2, c);
            fma4(s0, d, c2); fma4(s1, d2, c2);
        }
        s0 = warp_sum(s0); s1 = warp_sum(s1);
        if (lane == 0) { g_xpart[r0] = s0; g_xpart[r1] = s1; }
    }
}

// ============ K34': comb + gates (fused via semaphore) + LSTM ================
__global__ __launch_bounds__(256) void k34_mid(
        const float* __restrict__ comb_W, const float* __restrict__ comb_b,
        const float* __restrict__ W_ih, const float* __restrict__ b_ih,
        const float* __restrict__ b_hh, const float* __restrict__ c0,
        float* __restrict__ d_h, float* __restrict__ d_c) {
    pdl_trigger();
    int t = threadIdx.x, lane = t & 31, w = t >> 5, b = blockIdx.x;

    if (b < CB_BLKS) {
        int u = b * 8 + w;                       // [0,512)
        int r0 = u, r1 = u + 512;
        const float4* w0 = reinterpret_cast<const float4*>(comb_W) + (size_t)r0 * 512 + 128;
        const float4* w1 = reinterpret_cast<const float4*>(comb_W) + (size_t)r1 * 512 + 128;
        float4 wreg0[8], wreg1[8];
#pragma unroll
        for (int i = 0; i < 8; i++) {
            wreg0[i] = __ldcs(&w0[lane + 32 * i]);
            wreg1[i] = __ldcs(&w1[lane + 32 * i]);
        }
        pdl_wait();

        __shared__ float4 sat[256];
        if (t < 256) {
            float4 acc = make_float4(0.f, 0.f, 0.f, 0.f);
            const float4* p4 = reinterpret_cast<const float4*>(g_part);
#pragma unroll
            for (int p = 0; p < NPART; p++) {
                float4 x = p4[p * 256 + t];
                acc.x += x.x; acc.y += x.y; acc.z += x.z; acc.w += x.w;
            }
            sat[t] = acc;
        }
        __syncthreads();
        float s0 = 0.f, s1 = 0.f;
#pragma unroll
        for (int i = 0; i < 8; i++) {
            float4 c = sat[lane + 32 * i];
            fma4(s0, wreg0[i], c);
            fma4(s1, wreg1[i], c);
        }
        s0 = warp_sum(s0); s1 = warp_sum(s1);
        if (lane == 0) {
            g_x[r0] = fmaxf(s0 + g_xpart[r0] + comb_b[r0], 0.f);
            g_x[r1] = fmaxf(s1 + g_xpart[r1] + comb_b[r1], 0.f);
        }
        __syncthreads();
        if (t == 0) {
            __threadfence();
            atomicAdd(&g_sem_x, 1u);
        }
    } else {
        int u = (b - CB_BLKS) * 8 + w;           // [0,2048)
        int r0 = u, r1 = u + 2048;
        const float4* w0 = reinterpret_cast<const float4*>(W_ih) + (size_t)r0 * 256;
        const float4* w1 = reinterpret_cast<const float4*>(W_ih) + (size_t)r1 * 256;
        float4 wreg0[8], wreg1[8];
#pragma unroll
        for (int i = 0; i < 8; i++) {
            wreg0[i] = __ldcs(&w0[lane + 32 * i]);
            wreg1[i] = __ldcs(&w1[lane + 32 * i]);
        }
        pdl_wait();
        sem_spin(&g_sem_x, CB_BLKS);

        __shared__ float4 sx[256];
        __shared__ bool s_last;
        if (t < 256) sx[t] = reinterpret_cast<const float4*>(g_x)[t];
        __syncthreads();
        float s0 = 0.f, s1 = 0.f;
#pragma unroll
        for (int i = 0; i < 8; i++) {
            float4 c = sx[lane + 32 * i];
            fma4(s0, wreg0[i], c);
            fma4(s1, wreg1[i], c);
        }
        s0 = warp_sum(s0); s1 = warp_sum(s1);
        if (lane == 0) {
            g_gates[r0] = s0 + g_ghh[r0] + b_ih[r0] + b_hh[r0];
            g_gates[r1] = s1 + g_ghh[r1] + b_ih[r1] + b_hh[r1];
        }
        __syncthreads();

        if (t == 0) {
            __threadfence();
            unsigned old = atomicAdd(&g_sem_lstm, 1u);
            s_last = (old == GT_BLKS - 1);
            if (s_last) {
                g_sem_lstm = 0;
                g_sem_x = 0;
                g_sem_scores = 0;
            }
        }
        __syncthreads();
        if (s_last) {
            __threadfence();
#pragma unroll
            for (int r = 0; r < 4; r++) {
                int k = t + 256 * r;
                float gi = g_gates[k];
                float gf = g_gates[H + k];
                float gg = g_gates[2 * H + k];
                float go = g_gates[3 * H + k];
                float si = 1.f / (1.f + expf(-gi));
                float sf = 1.f / (1.f + expf(-gf));
                float so = 1.f / (1.f + expf(-go));
                float cn = sf * c0[k] + si * tanhf(gg);
                float hn = so * tanhf(cn);
                g_h[k] = hn;
                d_h[k] = hn;
                d_c[k] = cn;
            }
        }
    }
}

// ============ K5: logits — single base pointer, forced 4 blocks/SM ==========
__global__ __launch_bounds__(256, 4) void k5_logits(
        const float* __restrict__ out_W, const float* __restrict__ out_b,
        float* __restrict__ logits) {
    int t = threadIdx.x, lane = t & 31, w = t >> 5;

    // prologue: tail 40MB of out_W -> L2 evict_last during pre-logits window
    if (blockIdx.x < TPF_BLKS) {
        const char* p = (const char*)out_W + TPF_START
                        + (size_t)blockIdx.x * TPF_CHUNK + (size_t)t * 256;
        pf_last(p);
        pf_last(p + 128);
    }

    // 4 consecutive rows per warp from one base pointer; base clamped to V-4
    // so all loads stay in-bounds (tail groups recompute identical rows).
    int base = (blockIdx.x * 8 + w) * 4;
    int rb = base <= V - 4 ? base : V - 4;
    const float4* w0 = reinterpret_cast<const float4*>(out_W) + (size_t)rb * 256;
    pdl_wait();

    __shared__ float4 sh[H / 4];
    sh[t] = reinterpret_cast<const float4*>(g_h)[t];
    __syncthreads();
    float s0 = 0.f, s1 = 0.f, s2 = 0.f, s3 = 0.f;
#pragma unroll
    for (int i = 0; i < 8; i++) {
        int idx = lane + 32 * i;
        float4 a0 = __ldcs(&w0[idx]);
        float4 a1 = __ldcs(&w0[idx + 256]);
        float4 a2 = __ldcs(&w0[idx + 512]);
        float4 a3 = __ldcs(&w0[idx + 768]);
        float4 h = sh[idx];
        fma4(s0, a0, h); fma4(s1, a1, h);
        fma4(s2, a2, h); fma4(s3, a3, h);
    }
    s0 = warp_sum(s0); s1 = warp_sum(s1);
    s2 = warp_sum(s2); s3 = warp_sum(s3);
    if (lane == 0) {
        logits[rb]     = s0 + out_b[rb];
        logits[rb + 1] = s1 + out_b[rb + 1];
        logits[rb + 2] = s2 + out_b[rb + 2];
        logits[rb + 3] = s3 + out_b[rb + 3];
    }
}

// ---------------- launch: 3-kernel PDL chain ---------------------------------
extern "C" void kernel_launch(void* const* d_in, const int* in_sizes, int n_in,
                              void* d_out, int out_size) {
    (void)out_size;
    const int* word = (const int*)d_in[0];
    int k = (n_in >= 2 && in_sizes[1] == 1) ? 2 : 1;
    const float* av_emb  = (const float*)d_in[k + 0];
    const float* h0      = (const float*)d_in[k + 1];
    const float* c0      = (const float*)d_in[k + 2];
    const float* enc_out = (const float*)d_in[k + 3];
    const float* emb     = (const float*)d_in[k + 4];
    const float* attn_W  = (const float*)d_in[k + 5];
    const float* attn_b  = (const float*)d_in[k + 6];
    const float* comb_W  = (const float*)d_in[k + 7];
    const float* comb_b  = (const float*)d_in[k + 8];
    const float* W_ih    = (const float*)d_in[k + 9];
    const float* W_hh    = (const float*)d_in[k + 10];
    const float* b_ih    = (const float*)d_in[k + 11];
    const float* b_hh    = (const float*)d_in[k + 12];
    const float* out_W   = (const float*)d_in[k + 13];
    const float* out_b   = (const float*)d_in[k + 14];

    float* out = (float*)d_out;
    float* o_logits = out;              // [V]
    float* o_h      = out + V;          // [H]
    float* o_c      = out + V + H;      // [H]
    float* o_attn   = out + V + 2 * H;  // [L]

    cudaLaunchAttribute attr[1];
    attr[0].id = cudaLaunchAttributeProgrammaticStreamSerialization;
    attr[0].val.programmaticStreamSerializationAllowed = 1;

    cudaLaunchConfig_t cfg = {};
    cfg.blockDim = {256, 1, 1};
    cfg.dynamicSmemBytes = 0;
    cfg.stream = 0;
    cfg.attrs = attr;
    cfg.numAttrs = 1;

    k1_pre<<<K1_BLKS, 256>>>(word, emb, h0, av_emb, attn_W, attn_b, W_hh,
                             comb_W, enc_out, o_attn);

    cfg.gridDim = {K34_BLKS, 1, 1};
    cudaLaunchKernelEx(&cfg, k34_mid, comb_W, comb_b, W_ih, b_ih, b_hh, c0,
                       o_h, o_c);

    cfg.gridDim = {LOGIT_BLKS, 1, 1};
    cudaLaunchKernelEx(&cfg, k5_logits, out_W, out_b, o_logits);
}